// round 14
// baseline (speedup 1.0000x reference)
#include <cuda_runtime.h>
#include <cuda_bf16.h>
#include <math.h>
#include <stdint.h>

// ---------------- problem constants ----------------
#define BATCH   64
#define NSEQ    343
#define DIMC    384
#define NHEADS  12
#define HD      32
#define KDIM    384
#define QKV_N   1152
#define TABSZ   2197
#define CPBH    512
#define MTOT    (BATCH * NSEQ)      // 21952

// ---------------- scratch ----------------
__device__ float g_Q[(size_t)BATCH * NHEADS * NSEQ * HD];
__device__ float g_K[(size_t)BATCH * NHEADS * NSEQ * HD];
__device__ float g_V[(size_t)BATCH * NHEADS * NSEQ * HD];
__device__ float g_bias[(size_t)NHEADS * NSEQ * NSEQ];
__device__ float g_tableH[(size_t)TABSZ * NHEADS];

__device__ __nv_bfloat16 g_xhi[(size_t)MTOT * KDIM];
__device__ __nv_bfloat16 g_xlo[(size_t)MTOT * KDIM];
__device__ __nv_bfloat16 g_wqhi[(size_t)QKV_N * KDIM];
__device__ __nv_bfloat16 g_wqlo[(size_t)QKV_N * KDIM];
__device__ __nv_bfloat16 g_pwhi[(size_t)DIMC * KDIM];
__device__ __nv_bfloat16 g_pwlo[(size_t)DIMC * KDIM];
__device__ __nv_bfloat16 g_Ohi[(size_t)MTOT * DIMC];
__device__ __nv_bfloat16 g_Olo[(size_t)MTOT * DIMC];

__device__ __forceinline__ float warpSum(float v) {
    #pragma unroll
    for (int o = 16; o > 0; o >>= 1) v += __shfl_xor_sync(0xffffffffu, v, o);
    return v;
}

// ---------------- mma / async helpers ----------------
__device__ __forceinline__ void ldmatrix_x4(uint32_t& r0, uint32_t& r1,
                                            uint32_t& r2, uint32_t& r3, uint32_t addr) {
    asm volatile("ldmatrix.sync.aligned.m8n8.x4.shared.b16 {%0,%1,%2,%3}, [%4];"
        : "=r"(r0), "=r"(r1), "=r"(r2), "=r"(r3) : "r"(addr));
}
__device__ __forceinline__ void ldmatrix_x2(uint32_t& r0, uint32_t& r1, uint32_t addr) {
    asm volatile("ldmatrix.sync.aligned.m8n8.x2.shared.b16 {%0,%1}, [%2];"
        : "=r"(r0), "=r"(r1) : "r"(addr));
}
__device__ __forceinline__ void mma_bf16(float* c, const uint32_t* a, const uint32_t* b) {
    asm volatile("mma.sync.aligned.m16n8k16.row.col.f32.bf16.bf16.f32 "
        "{%0,%1,%2,%3}, {%4,%5,%6,%7}, {%8,%9}, {%0,%1,%2,%3};"
        : "+f"(c[0]), "+f"(c[1]), "+f"(c[2]), "+f"(c[3])
        : "r"(a[0]), "r"(a[1]), "r"(a[2]), "r"(a[3]), "r"(b[0]), "r"(b[1]));
}
__device__ __forceinline__ uint32_t pack2_hi(float a, float b) {
    __nv_bfloat162 t(__float2bfloat16(a), __float2bfloat16(b));
    return *(uint32_t*)&t;
}
__device__ __forceinline__ uint32_t pack2_lo(float a, float b) {
    float ha = __bfloat162float(__float2bfloat16(a));
    float hb = __bfloat162float(__float2bfloat16(b));
    __nv_bfloat162 t(__float2bfloat16(a - ha), __float2bfloat16(b - hb));
    return *(uint32_t*)&t;
}
__device__ __forceinline__ void cp_async16(uint32_t dst, const void* src, bool pred) {
    int sz = pred ? 16 : 0;
    asm volatile("cp.async.cg.shared.global [%0], [%1], 16, %2;"
        :: "r"(dst), "l"(src), "r"(sz));
}
__device__ __forceinline__ void cp_commit() {
    asm volatile("cp.async.commit_group;");
}
template <int N>
__device__ __forceinline__ void cp_wait() {
    asm volatile("cp.async.wait_group %0;" :: "n"(N));
}

// ---------------- split kernels ----------------
template <int DST>
__global__ void split_kernel(const float* __restrict__ src, int n4) {
    __nv_bfloat16* hi = (DST == 0) ? g_xhi : (DST == 1) ? g_wqhi : g_pwhi;
    __nv_bfloat16* lo = (DST == 0) ? g_xlo : (DST == 1) ? g_wqlo : g_pwlo;
    int i = blockIdx.x * blockDim.x + threadIdx.x;
    if (i >= n4) return;
    float4 v = ((const float4*)src)[i];
    __nv_bfloat16 h0 = __float2bfloat16(v.x);
    __nv_bfloat16 h1 = __float2bfloat16(v.y);
    __nv_bfloat16 h2 = __float2bfloat16(v.z);
    __nv_bfloat16 h3 = __float2bfloat16(v.w);
    __nv_bfloat162* hp = (__nv_bfloat162*)(hi + i * 4);
    __nv_bfloat162* lp = (__nv_bfloat162*)(lo + i * 4);
    hp[0] = __nv_bfloat162(h0, h1);
    hp[1] = __nv_bfloat162(h2, h3);
    lp[0] = __nv_bfloat162(__float2bfloat16(v.x - __bfloat162float(h0)),
                           __float2bfloat16(v.y - __bfloat162float(h1)));
    lp[1] = __nv_bfloat162(__float2bfloat16(v.z - __bfloat162float(h2)),
                           __float2bfloat16(v.w - __bfloat162float(h3)));
}

// ---------------- kernel 1: CPB MLP ----------------
__global__ void cpb_table_kernel(const float* __restrict__ tab,
                                 const float* __restrict__ w1,
                                 const float* __restrict__ b1,
                                 const float* __restrict__ w2) {
    __shared__ float hid[CPBH];
    int r = blockIdx.x;
    int tid = threadIdx.x;
    float t0 = tab[r * 3 + 0], t1 = tab[r * 3 + 1], t2 = tab[r * 3 + 2];
    float h = fmaf(w1[tid * 3 + 0], t0,
              fmaf(w1[tid * 3 + 1], t1,
              fmaf(w1[tid * 3 + 2], t2, b1[tid])));
    hid[tid] = fmaxf(h, 0.f);
    __syncthreads();
    int warp = tid >> 5, lane = tid & 31;
    if (warp < NHEADS) {
        float s = 0.f;
        #pragma unroll
        for (int j = lane; j < CPBH; j += 32) s = fmaf(hid[j], w2[warp * CPBH + j], s);
        s = warpSum(s);
        if (lane == 0) g_tableH[r * NHEADS + warp] = s;
    }
}

// ---------------- kernel 2: bias gather ----------------
__global__ void bias_gather_kernel(const int* __restrict__ idx) {
    int t = blockIdx.x * blockDim.x + threadIdx.x;
    const int NN = NSEQ * NSEQ;
    if (t >= NHEADS * NN) return;
    int h = t / NN;
    int ij = t - h * NN;
    float v = g_tableH[idx[ij] * NHEADS + h];
    g_bias[t] = 16.f / (1.f + __expf(-v));
}

// ---------------- tensor-core GEMM, cp.async 3-stage pipeline -------------
#define GBM 128
#define GBN 128
#define GBK 32
#define TSTR 40
#define NPASS 3
#define GSTAGES 3
#define GTILEB (GBM * TSTR * 2)
#define GEMM_SMEM (GSTAGES * 2 * GTILEB)

template <int MODE>
__global__ void __launch_bounds__(256, 2)
mma_gemm_kernel(const float* __restrict__ bias0, const float* __restrict__ bias1,
                float* __restrict__ Cout, int M) {
    const __nv_bfloat16* Ahi = (MODE == 0) ? g_xhi : g_Ohi;
    const __nv_bfloat16* Alo = (MODE == 0) ? g_xlo : g_Olo;
    const __nv_bfloat16* Bhi = (MODE == 0) ? g_wqhi : g_pwhi;
    const __nv_bfloat16* Blo = (MODE == 0) ? g_wqlo : g_pwlo;
    const __nv_bfloat16* Apass[NPASS] = {Ahi, Ahi, Alo};
    const __nv_bfloat16* Bpass[NPASS] = {Bhi, Blo, Bhi};

    extern __shared__ char gsm[];
    uint32_t sAu = (uint32_t)__cvta_generic_to_shared(gsm);
    uint32_t sBu = sAu + GSTAGES * GTILEB;

    int tid = threadIdx.x;
    int lane = tid & 31;
    int warp = tid >> 5;
    int wm = warp >> 2;
    int wn = warp & 3;
    int bm = blockIdx.x * GBM;
    int bn = blockIdx.y * GBN;

    int lrow = tid >> 1;
    int lk16 = (tid & 1) * 16;
    bool arow_ok = (bm + lrow) < M;

    const int NCH = NPASS * (KDIM / GBK);

    float acc[16][4];
    #pragma unroll
    for (int t = 0; t < 16; t++)
        #pragma unroll
        for (int j = 0; j < 4; j++) acc[t][j] = 0.f;

    auto issue = [&](int c, int s) {
        int pass = c / (KDIM / GBK);
        int kc = (c % (KDIM / GBK)) * GBK;
        const __nv_bfloat16* Ap = Apass[pass] + (size_t)(bm + lrow) * KDIM + kc + lk16;
        const __nv_bfloat16* Bp = Bpass[pass] + (size_t)(bn + lrow) * KDIM + kc + lk16;
        uint32_t da = sAu + s * GTILEB + (lrow * TSTR + lk16) * 2;
        uint32_t db = sBu + s * GTILEB + (lrow * TSTR + lk16) * 2;
        cp_async16(da, Ap, arow_ok);
        cp_async16(da + 16, Ap + 8, arow_ok);
        cp_async16(db, Bp, true);
        cp_async16(db + 16, Bp + 8, true);
        cp_commit();
    };

    issue(0, 0);
    issue(1, 1);

    for (int it = 0; it < NCH; it++) {
        if (it < NCH - 1) cp_wait<1>(); else cp_wait<0>();
        __syncthreads();
        if (it + 2 < NCH) issue(it + 2, (it + 2) % GSTAGES);

        uint32_t baseA = sAu + (it % GSTAGES) * GTILEB;
        uint32_t baseB = sBu + (it % GSTAGES) * GTILEB;
        #pragma unroll
        for (int ks = 0; ks < 2; ks++) {
            uint32_t af[4][4], bfr[4][2];
            #pragma unroll
            for (int mi = 0; mi < 4; mi++) {
                int row = wm * 64 + mi * 16 + (lane & 15);
                int kb = ks * 16 + ((lane >> 4) << 3);
                ldmatrix_x4(af[mi][0], af[mi][1], af[mi][2], af[mi][3],
                            baseA + (row * TSTR + kb) * 2);
            }
            #pragma unroll
            for (int bj = 0; bj < 2; bj++) {
                int nrow = wn * 32 + bj * 16 + (lane & 7) + ((lane >> 4) << 3);
                int kb = ks * 16 + (((lane >> 3) & 1) << 3);
                uint32_t r0, r1, r2, r3;
                ldmatrix_x4(r0, r1, r2, r3, baseB + (nrow * TSTR + kb) * 2);
                bfr[bj * 2][0] = r0; bfr[bj * 2][1] = r1;
                bfr[bj * 2 + 1][0] = r2; bfr[bj * 2 + 1][1] = r3;
            }
            #pragma unroll
            for (int mi = 0; mi < 4; mi++)
                #pragma unroll
                for (int nj = 0; nj < 4; nj++)
                    mma_bf16(acc[mi * 4 + nj], af[mi], bfr[nj]);
        }
    }

    #pragma unroll
    for (int mi = 0; mi < 4; mi++) {
        #pragma unroll
        for (int nj = 0; nj < 4; nj++) {
            int col = bn + wn * 32 + nj * 8 + ((lane & 3) << 1);
            float* cr = acc[mi * 4 + nj];
            #pragma unroll
            for (int half = 0; half < 2; half++) {
                int m = bm + wm * 64 + mi * 16 + (lane >> 2) + half * 8;
                if (m >= M) continue;
                float v0 = cr[half * 2 + 0];
                float v1 = cr[half * 2 + 1];
                if (MODE == 0) {
                    int part = col / DIMC;
                    int oc = col - part * DIMC;
                    int hh = oc >> 5, d = oc & 31;
                    if (part == 0) { v0 += bias0[oc]; v1 += bias0[oc + 1]; }
                    else if (part == 2) { v0 += bias1[oc]; v1 += bias1[oc + 1]; }
                    int bw = m / NSEQ, nn = m - bw * NSEQ;
                    size_t dst = ((size_t)(bw * NHEADS + hh) * NSEQ + nn) * HD + d;
                    float* tgt = (part == 0) ? g_Q : (part == 1 ? g_K : g_V);
                    *(float2*)(tgt + dst) = make_float2(v0, v1);
                } else {
                    v0 += bias0[col];
                    v1 += bias0[col + 1];
                    *(float2*)(Cout + (size_t)m * DIMC + col) = make_float2(v0, v1);
                }
            }
        }
    }
}

// ---------------- kernel 4: persistent-window attention --------------------
#define QT 64
#define NP 352
#define AQ_STR 40
#define AP_STR 360
#define ATTN_THREADS 512
#define NQT ((NSEQ + QT - 1) / QT)   // 6
#define SO_STR 33
// K 56320 + V 46080 + Q 10240 + sRedP 2048 + 2x sOp 33792
#define ATTN_SMEM ((2*NP*AQ_STR + 2*HD*AP_STR + 2*QT*AQ_STR)*2 + 2*QT*4*4 + 2*4*QT*SO_STR*4)

__global__ void __launch_bounds__(ATTN_THREADS, 1)
attn_kernel(const float* __restrict__ mask, const float* __restrict__ logit_scale) {
    extern __shared__ char smraw[];
    __nv_bfloat16* sKhi = (__nv_bfloat16*)smraw;
    __nv_bfloat16* sKlo = sKhi + NP * AQ_STR;
    __nv_bfloat16* sVhi = sKlo + NP * AQ_STR;
    __nv_bfloat16* sVlo = sVhi + HD * AP_STR;
    __nv_bfloat16* sQhi = sVlo + HD * AP_STR;
    __nv_bfloat16* sQlo = sQhi + QT * AQ_STR;
    float2* sRedP = (float2*)(sQlo + QT * AQ_STR);     // 64*4 float2 = 2048 B
    float* sOp0 = (float*)(sRedP + QT * 4);            // 2 buffers x 4 x (64 x 33)

    int h  = blockIdx.x;
    int bw = blockIdx.y;
    int tid = threadIdx.x;
    int lane = tid & 31;
    int warp = tid >> 5;
    size_t headBase = ((size_t)(bw * NHEADS + h) * NSEQ) * HD;

    const float* Kg = g_K + headBase;
    const float* Vg = g_V + headBase;
    const float* Qg = g_Q + headBase;

    int rsub = tid & 7;
    int rgrp = tid >> 3;

    // ---- K: load + normalize + split (uniform 6 iters; shfl all lanes) ----
    #pragma unroll
    for (int it = 0; it < 6; it++) {
        int r = rgrp + it * 64;
        bool ok = r < NSEQ;
        float4 v = make_float4(0.f, 0.f, 0.f, 0.f);
        if (ok) v = *(const float4*)(Kg + r * HD + rsub * 4);
        float ss = v.x * v.x + v.y * v.y + v.z * v.z + v.w * v.w;
        ss += __shfl_xor_sync(0xffffffffu, ss, 1);
        ss += __shfl_xor_sync(0xffffffffu, ss, 2);
        ss += __shfl_xor_sync(0xffffffffu, ss, 4);
        float invn = 1.f / fmaxf(sqrtf(ss), 1e-12f);
        if (ok) {
            float n0 = v.x * invn, n1 = v.y * invn, n2 = v.z * invn, n3 = v.w * invn;
            int off = r * AQ_STR + rsub * 4;
            *(uint32_t*)&sKhi[off]     = pack2_hi(n0, n1);
            *(uint32_t*)&sKhi[off + 2] = pack2_hi(n2, n3);
            *(uint32_t*)&sKlo[off]     = pack2_lo(n0, n1);
            *(uint32_t*)&sKlo[off + 2] = pack2_lo(n2, n3);
        }
    }
    for (int e = tid; e < (NP - NSEQ) * HD; e += ATTN_THREADS) {
        int r = NSEQ + (e >> 5), d = e & 31;
        sKhi[r * AQ_STR + d] = __float2bfloat16(0.f);
        sKlo[r * AQ_STR + d] = __float2bfloat16(0.f);
    }
    // ---- V: transpose + split; pad through full AP_STR ----
    for (int e = tid; e < NSEQ * HD; e += ATTN_THREADS) {
        int j = e >> 5, d = e & 31;
        float v = Vg[e];
        __nv_bfloat16 hi = __float2bfloat16(v);
        sVhi[d * AP_STR + j] = hi;
        sVlo[d * AP_STR + j] = __float2bfloat16(v - __bfloat162float(hi));
    }
    for (int e = tid; e < HD * (AP_STR - NSEQ); e += ATTN_THREADS) {
        int d = e / (AP_STR - NSEQ), j = NSEQ + e % (AP_STR - NSEQ);
        sVhi[d * AP_STR + j] = __float2bfloat16(0.f);
        sVlo[d * AP_STR + j] = __float2bfloat16(0.f);
    }
    __syncthreads();

    int wm = warp & 3;
    int wn = warp >> 2;
    uint32_t uQhi = (uint32_t)__cvta_generic_to_shared(sQhi);
    uint32_t uQlo = (uint32_t)__cvta_generic_to_shared(sQlo);
    uint32_t uKhi = (uint32_t)__cvta_generic_to_shared(sKhi);
    uint32_t uKlo = (uint32_t)__cvta_generic_to_shared(sKlo);
    uint32_t uVhi = (uint32_t)__cvta_generic_to_shared(sVhi);
    uint32_t uVlo = (uint32_t)__cvta_generic_to_shared(sVlo);

    float scale = __expf(fminf(logit_scale[h], 4.6051702f));
    int r0 = wm * 16 + (lane >> 2);

    for (int qt = 0; qt < NQT; qt++) {
        int qbase = qt * QT;
        float* sOp = sOp0 + (qt & 1) * (4 * QT * SO_STR);

        // ---- Q tile: load + normalize(*scale) + split, one pass ----
        {
            int gi = qbase + rgrp;
            float4 v = make_float4(0.f, 0.f, 0.f, 0.f);
            if (gi < NSEQ) v = *(const float4*)(Qg + gi * HD + rsub * 4);
            float ss = v.x * v.x + v.y * v.y + v.z * v.z + v.w * v.w;
            ss += __shfl_xor_sync(0xffffffffu, ss, 1);
            ss += __shfl_xor_sync(0xffffffffu, ss, 2);
            ss += __shfl_xor_sync(0xffffffffu, ss, 4);
            float invn = scale / fmaxf(sqrtf(ss), 1e-12f);
            float n0 = v.x * invn, n1 = v.y * invn, n2 = v.z * invn, n3 = v.w * invn;
            int off = rgrp * AQ_STR + rsub * 4;
            *(uint32_t*)&sQhi[off]     = pack2_hi(n0, n1);
            *(uint32_t*)&sQhi[off + 2] = pack2_hi(n2, n3);
            *(uint32_t*)&sQlo[off]     = pack2_lo(n0, n1);
            *(uint32_t*)&sQlo[off + 2] = pack2_lo(n2, n3);
        }

        // ---- prefetch bias+mask (scalar; row bases only 4B-aligned) ----
        float2 bm[2][11];
        #pragma unroll
        for (int half = 0; half < 2; half++) {
            int gi = qbase + r0 + half * 8;
            bool rok = gi < NSEQ;
            const float* brow = g_bias + ((size_t)h * NSEQ + gi) * NSEQ;
            const float* mrow = mask + ((size_t)bw * NSEQ + gi) * NSEQ;
            #pragma unroll
            for (int t = 0; t < 11; t++) {
                int j0 = wn * 88 + t * 8 + ((lane & 3) << 1);
                float2 v = make_float2(0.f, 0.f);
                if (rok && j0 < NSEQ)     v.x = brow[j0] + mrow[j0];
                if (rok && j0 + 1 < NSEQ) v.y = brow[j0 + 1] + mrow[j0 + 1];
                bm[half][t] = v;
            }
        }
        __syncthreads();

        // ---- scores (3-pass split mma); scale folded into Q ----
        float acc[11][4];
        #pragma unroll
        for (int t = 0; t < 11; t++)
            #pragma unroll
            for (int j = 0; j < 4; j++) acc[t][j] = 0.f;
        {
            uint32_t aB[3] = {uQhi, uQhi, uQlo};
            uint32_t bB[3] = {uKhi, uKlo, uKhi};
            #pragma unroll
            for (int p = 0; p < 3; p++) {
                #pragma unroll
                for (int ks = 0; ks < 2; ks++) {
                    uint32_t a[4];
                    int arow = wm * 16 + (lane & 15);
                    int akc = ks * 16 + ((lane >> 4) << 3);
                    ldmatrix_x4(a[0], a[1], a[2], a[3], aB[p] + (arow * AQ_STR + akc) * 2);
                    int kb = ks * 16 + (((lane >> 3) & 1) << 3);
                    #pragma unroll
                    for (int t2 = 0; t2 < 5; t2++) {
                        int nrow = wn * 88 + t2 * 16 + (lane & 7) + ((lane >> 4) << 3);
                        uint32_t r0_, r1_, r2_, r3_;
                        ldmatrix_x4(r0_, r1_, r2_, r3_, bB[p] + (nrow * AQ_STR + kb) * 2);
                        uint32_t b0[2] = {r0_, r1_}, b1[2] = {r2_, r3_};
                        mma_bf16(acc[t2 * 2], a, b0);
                        mma_bf16(acc[t2 * 2 + 1], a, b1);
                    }
                    {
                        int nrow = wn * 88 + 80 + (lane & 7);
                        uint32_t r0_, r1_;
                        ldmatrix_x2(r0_, r1_, bB[p] + (nrow * AQ_STR + kb) * 2);
                        uint32_t b0[2] = {r0_, r1_};
                        mma_bf16(acc[10], a, b0);
                    }
                }
            }
        }

        // ---- online softmax: add bias, local max, exp, local sum, ONE sync --
        float mloc[2];
        #pragma unroll
        for (int half = 0; half < 2; half++) {
            int gi = qbase + r0 + half * 8;
            float m = -1e30f;
            if (gi < NSEQ) {
                #pragma unroll
                for (int t = 0; t < 11; t++) {
                    int j0 = wn * 88 + t * 8 + ((lane & 3) << 1);
                    if (j0 < NSEQ) {
                        float s = acc[t][half * 2] + bm[half][t].x;
                        acc[t][half * 2] = s;
                        m = fmaxf(m, s);
                    }
                    if (j0 + 1 < NSEQ) {
                        float s = acc[t][half * 2 + 1] + bm[half][t].y;
                        acc[t][half * 2 + 1] = s;
                        m = fmaxf(m, s);
                    }
                }
            }
            m = fmaxf(m, __shfl_xor_sync(0xffffffffu, m, 1));
            m = fmaxf(m, __shfl_xor_sync(0xffffffffu, m, 2));
            mloc[half] = m;
            float ls = 0.f;
            if (gi < NSEQ) {
                #pragma unroll
                for (int t = 0; t < 11; t++) {
                    int j0 = wn * 88 + t * 8 + ((lane & 3) << 1);
                    if (j0 < NSEQ) {
                        float p = __expf(acc[t][half * 2] - m);
                        acc[t][half * 2] = p;
                        ls += p;
                    }
                    if (j0 + 1 < NSEQ) {
                        float p = __expf(acc[t][half * 2 + 1] - m);
                        acc[t][half * 2 + 1] = p;
                        ls += p;
                    }
                }
            }
            ls += __shfl_xor_sync(0xffffffffu, ls, 1);
            ls += __shfl_xor_sync(0xffffffffu, ls, 2);
            int r = r0 + half * 8;
            if ((lane & 3) == 0) sRedP[r * 4 + wn] = make_float2(m, ls);
        }
        __syncthreads();

        // ---- combine per-warp (m, ls), fold into P scale factor ----
        float fscale[2];
        #pragma unroll
        for (int half = 0; half < 2; half++) {
            int r = r0 + half * 8;
            int gi = qbase + r;
            float2 p0 = sRedP[r * 4 + 0];
            float2 p1 = sRedP[r * 4 + 1];
            float2 p2 = sRedP[r * 4 + 2];
            float2 p3 = sRedP[r * 4 + 3];
            float mg = fmaxf(fmaxf(p0.x, p1.x), fmaxf(p2.x, p3.x));
            float total = p0.y * __expf(p0.x - mg) + p1.y * __expf(p1.x - mg)
                        + p2.y * __expf(p2.x - mg) + p3.y * __expf(p3.x - mg);
            fscale[half] = (gi < NSEQ) ? (__expf(mloc[half] - mg) / total) : 0.f;
        }

        // ---- pack P fragments in registers ----
        uint32_t phi[6][4], plo[6][4];
        #pragma unroll
        for (int ks = 0; ks < 6; ks++) {
            #pragma unroll
            for (int idx = 0; idx < 4; idx++) {
                int t = 2 * ks + (idx >> 1);
                int half = idx & 1;
                float p0 = 0.f, p1 = 0.f;
                if (t <= 10) {
                    int j0 = wn * 88 + t * 8 + ((lane & 3) << 1);
                    if (j0 < NSEQ)     p0 = acc[t][half * 2] * fscale[half];
                    if (j0 + 1 < NSEQ) p1 = acc[t][half * 2 + 1] * fscale[half];
                }
                phi[ks][idx] = pack2_hi(p0, p1);
                plo[ks][idx] = pack2_lo(p0, p1);
            }
        }

        // ---- PV: each warp over its 96-col k-slice ----
        float oacc[4][4];
        #pragma unroll
        for (int dt = 0; dt < 4; dt++)
            #pragma unroll
            for (int j = 0; j < 4; j++) oacc[dt][j] = 0.f;
        {
            int g = lane >> 3;
            int vrow_lo = (g >> 1) * 8 + (lane & 7);
            int koff = (g & 1) * 8;
            #pragma unroll
            for (int ks = 0; ks < 6; ks++) {
                int kb = wn * 88 + ks * 16 + koff;
                #pragma unroll
                for (int e = 0; e < 2; e++) {
                    int vrow = 16 * e + vrow_lo;
                    uint32_t h0, h1, h2, h3;
                    ldmatrix_x4(h0, h1, h2, h3, uVhi + (vrow * AP_STR + kb) * 2);
                    uint32_t bt0[2] = {h0, h1}, bt1[2] = {h2, h3};
                    mma_bf16(oacc[2 * e],     phi[ks], bt0);
                    mma_bf16(oacc[2 * e + 1], phi[ks], bt1);
                    mma_bf16(oacc[2 * e],     plo[ks], bt0);
                    mma_bf16(oacc[2 * e + 1], plo[ks], bt1);
                    uint32_t l0, l1, l2, l3;
                    ldmatrix_x4(l0, l1, l2, l3, uVlo + (vrow * AP_STR + kb) * 2);
                    uint32_t bl0[2] = {l0, l1}, bl1[2] = {l2, l3};
                    mma_bf16(oacc[2 * e],     phi[ks], bl0);
                    mma_bf16(oacc[2 * e + 1], phi[ks], bl1);
                }
            }
        }
        #pragma unroll
        for (int dt = 0; dt < 4; dt++) {
            int d0 = dt * 8 + ((lane & 3) << 1);
            #pragma unroll
            for (int half = 0; half < 2; half++) {
                int r = r0 + half * 8;
                float* dst = sOp + wn * (QT * SO_STR) + r * SO_STR + d0;
                dst[0] = oacc[dt][half * 2];
                dst[1] = oacc[dt][half * 2 + 1];
            }
        }
        __syncthreads();

        // ---- store O tile (sum 4 partials, split bf16); no trailing sync
        //      (sOp double-buffered; next same-buffer write is 2 barriers away)
        for (int o = tid; o < QT * HD; o += ATTN_THREADS) {
            int row = o >> 5, d = o & 31;
            int gi = qbase + row;
            if (gi >= NSEQ) continue;
            int base = row * SO_STR + d;
            float v = sOp[base]
                    + sOp[1 * (QT * SO_STR) + base]
                    + sOp[2 * (QT * SO_STR) + base]
                    + sOp[3 * (QT * SO_STR) + base];
            size_t oidx = ((size_t)bw * NSEQ + gi) * DIMC + h * HD + d;
            __nv_bfloat16 hv = __float2bfloat16(v);
            g_Ohi[oidx] = hv;
            g_Olo[oidx] = __float2bfloat16(v - __bfloat162float(hv));
        }
    }
}

// ---------------- launch -----------------------------------------------------
extern "C" void kernel_launch(void* const* d_in, const int* in_sizes, int n_in,
                              void* d_out, int out_size) {
    const float* x        = (const float*)d_in[0];
    const float* mask     = (const float*)d_in[1];
    const float* qkv_w    = (const float*)d_in[2];
    const float* q_bias   = (const float*)d_in[3];
    const float* v_bias   = (const float*)d_in[4];
    const float* lscale   = (const float*)d_in[5];
    const float* cpb_w1   = (const float*)d_in[6];
    const float* cpb_b1   = (const float*)d_in[7];
    const float* cpb_w2   = (const float*)d_in[8];
    const float* proj_w   = (const float*)d_in[9];
    const float* proj_b   = (const float*)d_in[10];
    const float* rel_tab  = (const float*)d_in[11];
    const int*   rel_idx  = (const int*)d_in[12];
    float* out = (float*)d_out;

    const int M = MTOT;

    {
        int n4 = M * KDIM / 4;
        split_kernel<0><<<(n4 + 255) / 256, 256>>>(x, n4);
        n4 = QKV_N * KDIM / 4;
        split_kernel<1><<<(n4 + 255) / 256, 256>>>(qkv_w, n4);
        n4 = DIMC * KDIM / 4;
        split_kernel<2><<<(n4 + 255) / 256, 256>>>(proj_w, n4);
    }

    cpb_table_kernel<<<TABSZ, CPBH>>>(rel_tab, cpb_w1, cpb_b1, cpb_w2);

    {
        int total = NHEADS * NSEQ * NSEQ;
        bias_gather_kernel<<<(total + 255) / 256, 256>>>(rel_idx);
    }

    {
        cudaFuncSetAttribute(mma_gemm_kernel<0>,
                             cudaFuncAttributeMaxDynamicSharedMemorySize, GEMM_SMEM);
        dim3 grid((M + GBM - 1) / GBM, QKV_N / GBN);
        mma_gemm_kernel<0><<<grid, 256, GEMM_SMEM>>>(q_bias, v_bias, nullptr, M);
    }

    {
        cudaFuncSetAttribute(attn_kernel,
                             cudaFuncAttributeMaxDynamicSharedMemorySize, ATTN_SMEM);
        dim3 grid(NHEADS, BATCH);
        attn_kernel<<<grid, ATTN_THREADS, ATTN_SMEM>>>(mask, lscale);
    }

    {
        cudaFuncSetAttribute(mma_gemm_kernel<1>,
                             cudaFuncAttributeMaxDynamicSharedMemorySize, GEMM_SMEM);
        dim3 grid((M + GBM - 1) / GBM, DIMC / GBN);
        mma_gemm_kernel<1><<<grid, 256, GEMM_SMEM>>>(proj_b, nullptr, out, M);
    }
}

// round 15
// speedup vs baseline: 1.0293x; 1.0293x over previous
#include <cuda_runtime.h>
#include <cuda_bf16.h>
#include <math.h>
#include <stdint.h>

// ---------------- problem constants ----------------
#define BATCH   64
#define NSEQ    343
#define DIMC    384
#define NHEADS  12
#define HD      32
#define KDIM    384
#define QKV_N   1152
#define TABSZ   2197
#define CPBH    512
#define MTOT    (BATCH * NSEQ)      // 21952

// ---------------- scratch ----------------
__device__ float g_Q[(size_t)BATCH * NHEADS * NSEQ * HD];
__device__ float g_K[(size_t)BATCH * NHEADS * NSEQ * HD];
__device__ float g_V[(size_t)BATCH * NHEADS * NSEQ * HD];
__device__ float g_bias[(size_t)NHEADS * NSEQ * NSEQ];
__device__ float g_tableH[(size_t)TABSZ * NHEADS];

__device__ __nv_bfloat16 g_xhi[(size_t)MTOT * KDIM];
__device__ __nv_bfloat16 g_xlo[(size_t)MTOT * KDIM];
__device__ __nv_bfloat16 g_wqhi[(size_t)QKV_N * KDIM];
__device__ __nv_bfloat16 g_wqlo[(size_t)QKV_N * KDIM];
__device__ __nv_bfloat16 g_pwhi[(size_t)DIMC * KDIM];
__device__ __nv_bfloat16 g_pwlo[(size_t)DIMC * KDIM];
__device__ __nv_bfloat16 g_Ohi[(size_t)MTOT * DIMC];
__device__ __nv_bfloat16 g_Olo[(size_t)MTOT * DIMC];

__device__ __forceinline__ float warpSum(float v) {
    #pragma unroll
    for (int o = 16; o > 0; o >>= 1) v += __shfl_xor_sync(0xffffffffu, v, o);
    return v;
}

// ---------------- mma / async helpers ----------------
__device__ __forceinline__ void ldmatrix_x4(uint32_t& r0, uint32_t& r1,
                                            uint32_t& r2, uint32_t& r3, uint32_t addr) {
    asm volatile("ldmatrix.sync.aligned.m8n8.x4.shared.b16 {%0,%1,%2,%3}, [%4];"
        : "=r"(r0), "=r"(r1), "=r"(r2), "=r"(r3) : "r"(addr));
}
__device__ __forceinline__ void ldmatrix_x2(uint32_t& r0, uint32_t& r1, uint32_t addr) {
    asm volatile("ldmatrix.sync.aligned.m8n8.x2.shared.b16 {%0,%1}, [%2];"
        : "=r"(r0), "=r"(r1) : "r"(addr));
}
__device__ __forceinline__ void mma_bf16(float* c, const uint32_t* a, const uint32_t* b) {
    asm volatile("mma.sync.aligned.m16n8k16.row.col.f32.bf16.bf16.f32 "
        "{%0,%1,%2,%3}, {%4,%5,%6,%7}, {%8,%9}, {%0,%1,%2,%3};"
        : "+f"(c[0]), "+f"(c[1]), "+f"(c[2]), "+f"(c[3])
        : "r"(a[0]), "r"(a[1]), "r"(a[2]), "r"(a[3]), "r"(b[0]), "r"(b[1]));
}
__device__ __forceinline__ uint32_t pack2_hi(float a, float b) {
    __nv_bfloat162 t(__float2bfloat16(a), __float2bfloat16(b));
    return *(uint32_t*)&t;
}
__device__ __forceinline__ uint32_t pack2_lo(float a, float b) {
    float ha = __bfloat162float(__float2bfloat16(a));
    float hb = __bfloat162float(__float2bfloat16(b));
    __nv_bfloat162 t(__float2bfloat16(a - ha), __float2bfloat16(b - hb));
    return *(uint32_t*)&t;
}
__device__ __forceinline__ void cp_async16(uint32_t dst, const void* src, bool pred) {
    int sz = pred ? 16 : 0;
    asm volatile("cp.async.cg.shared.global [%0], [%1], 16, %2;"
        :: "r"(dst), "l"(src), "r"(sz));
}
__device__ __forceinline__ void cp_commit() {
    asm volatile("cp.async.commit_group;");
}
template <int N>
__device__ __forceinline__ void cp_wait() {
    asm volatile("cp.async.wait_group %0;" :: "n"(N));
}

// ---------------- fused split kernel: x | qkv_w | proj_w ------------------
#define N4_X   (MTOT * KDIM / 4)
#define N4_WQ  (QKV_N * KDIM / 4)
#define N4_PW  (DIMC * KDIM / 4)
#define N4_ALL (N4_X + N4_WQ + N4_PW)

__global__ void split_all_kernel(const float* __restrict__ x,
                                 const float* __restrict__ qkv_w,
                                 const float* __restrict__ proj_w) {
    int i = blockIdx.x * blockDim.x + threadIdx.x;
    if (i >= N4_ALL) return;
    const float* src;
    __nv_bfloat16 *hi, *lo;
    int k;
    if (i < N4_X) {
        src = x; hi = g_xhi; lo = g_xlo; k = i;
    } else if (i < N4_X + N4_WQ) {
        src = qkv_w; hi = g_wqhi; lo = g_wqlo; k = i - N4_X;
    } else {
        src = proj_w; hi = g_pwhi; lo = g_pwlo; k = i - N4_X - N4_WQ;
    }
    float4 v = ((const float4*)src)[k];
    __nv_bfloat16 h0 = __float2bfloat16(v.x);
    __nv_bfloat16 h1 = __float2bfloat16(v.y);
    __nv_bfloat16 h2 = __float2bfloat16(v.z);
    __nv_bfloat16 h3 = __float2bfloat16(v.w);
    __nv_bfloat162* hp = (__nv_bfloat162*)(hi + (size_t)k * 4);
    __nv_bfloat162* lp = (__nv_bfloat162*)(lo + (size_t)k * 4);
    hp[0] = __nv_bfloat162(h0, h1);
    hp[1] = __nv_bfloat162(h2, h3);
    lp[0] = __nv_bfloat162(__float2bfloat16(v.x - __bfloat162float(h0)),
                           __float2bfloat16(v.y - __bfloat162float(h1)));
    lp[1] = __nv_bfloat162(__float2bfloat16(v.z - __bfloat162float(h2)),
                           __float2bfloat16(v.w - __bfloat162float(h3)));
}

// ---------------- kernel 1: CPB MLP ----------------
__global__ void cpb_table_kernel(const float* __restrict__ tab,
                                 const float* __restrict__ w1,
                                 const float* __restrict__ b1,
                                 const float* __restrict__ w2) {
    __shared__ float hid[CPBH];
    int r = blockIdx.x;
    int tid = threadIdx.x;
    float t0 = tab[r * 3 + 0], t1 = tab[r * 3 + 1], t2 = tab[r * 3 + 2];
    float h = fmaf(w1[tid * 3 + 0], t0,
              fmaf(w1[tid * 3 + 1], t1,
              fmaf(w1[tid * 3 + 2], t2, b1[tid])));
    hid[tid] = fmaxf(h, 0.f);
    __syncthreads();
    int warp = tid >> 5, lane = tid & 31;
    if (warp < NHEADS) {
        float s = 0.f;
        #pragma unroll
        for (int j = lane; j < CPBH; j += 32) s = fmaf(hid[j], w2[warp * CPBH + j], s);
        s = warpSum(s);
        if (lane == 0) g_tableH[r * NHEADS + warp] = s;
    }
}

// ---------------- kernel 2: bias gather ----------------
__global__ void bias_gather_kernel(const int* __restrict__ idx) {
    int t = blockIdx.x * blockDim.x + threadIdx.x;
    const int NN = NSEQ * NSEQ;
    if (t >= NHEADS * NN) return;
    int h = t / NN;
    int ij = t - h * NN;
    float v = g_tableH[idx[ij] * NHEADS + h];
    g_bias[t] = 16.f / (1.f + __expf(-v));
}

// ---------------- tensor-core GEMM, cp.async 3-stage pipeline -------------
#define GBM 128
#define GBN 128
#define GBK 32
#define TSTR 40
#define NPASS 3
#define GSTAGES 3
#define GTILEB (GBM * TSTR * 2)
#define GEMM_SMEM (GSTAGES * 2 * GTILEB)

template <int MODE>
__global__ void __launch_bounds__(256, 2)
mma_gemm_kernel(const float* __restrict__ bias0, const float* __restrict__ bias1,
                float* __restrict__ Cout, int M) {
    const __nv_bfloat16* Ahi = (MODE == 0) ? g_xhi : g_Ohi;
    const __nv_bfloat16* Alo = (MODE == 0) ? g_xlo : g_Olo;
    const __nv_bfloat16* Bhi = (MODE == 0) ? g_wqhi : g_pwhi;
    const __nv_bfloat16* Blo = (MODE == 0) ? g_wqlo : g_pwlo;
    const __nv_bfloat16* Apass[NPASS] = {Ahi, Ahi, Alo};
    const __nv_bfloat16* Bpass[NPASS] = {Bhi, Blo, Bhi};

    extern __shared__ char gsm[];
    uint32_t sAu = (uint32_t)__cvta_generic_to_shared(gsm);
    uint32_t sBu = sAu + GSTAGES * GTILEB;

    int tid = threadIdx.x;
    int lane = tid & 31;
    int warp = tid >> 5;
    int wm = warp >> 2;
    int wn = warp & 3;
    int bm = blockIdx.x * GBM;
    int bn = blockIdx.y * GBN;

    int lrow = tid >> 1;
    int lk16 = (tid & 1) * 16;
    bool arow_ok = (bm + lrow) < M;

    const int NCH = NPASS * (KDIM / GBK);

    float acc[16][4];
    #pragma unroll
    for (int t = 0; t < 16; t++)
        #pragma unroll
        for (int j = 0; j < 4; j++) acc[t][j] = 0.f;

    auto issue = [&](int c, int s) {
        int pass = c / (KDIM / GBK);
        int kc = (c % (KDIM / GBK)) * GBK;
        const __nv_bfloat16* Ap = Apass[pass] + (size_t)(bm + lrow) * KDIM + kc + lk16;
        const __nv_bfloat16* Bp = Bpass[pass] + (size_t)(bn + lrow) * KDIM + kc + lk16;
        uint32_t da = sAu + s * GTILEB + (lrow * TSTR + lk16) * 2;
        uint32_t db = sBu + s * GTILEB + (lrow * TSTR + lk16) * 2;
        cp_async16(da, Ap, arow_ok);
        cp_async16(da + 16, Ap + 8, arow_ok);
        cp_async16(db, Bp, true);
        cp_async16(db + 16, Bp + 8, true);
        cp_commit();
    };

    issue(0, 0);
    issue(1, 1);

    for (int it = 0; it < NCH; it++) {
        if (it < NCH - 1) cp_wait<1>(); else cp_wait<0>();
        __syncthreads();
        if (it + 2 < NCH) issue(it + 2, (it + 2) % GSTAGES);

        uint32_t baseA = sAu + (it % GSTAGES) * GTILEB;
        uint32_t baseB = sBu + (it % GSTAGES) * GTILEB;
        #pragma unroll
        for (int ks = 0; ks < 2; ks++) {
            uint32_t af[4][4], bfr[4][2];
            #pragma unroll
            for (int mi = 0; mi < 4; mi++) {
                int row = wm * 64 + mi * 16 + (lane & 15);
                int kb = ks * 16 + ((lane >> 4) << 3);
                ldmatrix_x4(af[mi][0], af[mi][1], af[mi][2], af[mi][3],
                            baseA + (row * TSTR + kb) * 2);
            }
            #pragma unroll
            for (int bj = 0; bj < 2; bj++) {
                int nrow = wn * 32 + bj * 16 + (lane & 7) + ((lane >> 4) << 3);
                int kb = ks * 16 + (((lane >> 3) & 1) << 3);
                uint32_t r0, r1, r2, r3;
                ldmatrix_x4(r0, r1, r2, r3, baseB + (nrow * TSTR + kb) * 2);
                bfr[bj * 2][0] = r0; bfr[bj * 2][1] = r1;
                bfr[bj * 2 + 1][0] = r2; bfr[bj * 2 + 1][1] = r3;
            }
            #pragma unroll
            for (int mi = 0; mi < 4; mi++)
                #pragma unroll
                for (int nj = 0; nj < 4; nj++)
                    mma_bf16(acc[mi * 4 + nj], af[mi], bfr[nj]);
        }
    }

    #pragma unroll
    for (int mi = 0; mi < 4; mi++) {
        #pragma unroll
        for (int nj = 0; nj < 4; nj++) {
            int col = bn + wn * 32 + nj * 8 + ((lane & 3) << 1);
            float* cr = acc[mi * 4 + nj];
            #pragma unroll
            for (int half = 0; half < 2; half++) {
                int m = bm + wm * 64 + mi * 16 + (lane >> 2) + half * 8;
                if (m >= M) continue;
                float v0 = cr[half * 2 + 0];
                float v1 = cr[half * 2 + 1];
                if (MODE == 0) {
                    int part = col / DIMC;
                    int oc = col - part * DIMC;
                    int hh = oc >> 5, d = oc & 31;
                    if (part == 0) { v0 += bias0[oc]; v1 += bias0[oc + 1]; }
                    else if (part == 2) { v0 += bias1[oc]; v1 += bias1[oc + 1]; }
                    int bw = m / NSEQ, nn = m - bw * NSEQ;
                    size_t dst = ((size_t)(bw * NHEADS + hh) * NSEQ + nn) * HD + d;
                    float* tgt = (part == 0) ? g_Q : (part == 1 ? g_K : g_V);
                    *(float2*)(tgt + dst) = make_float2(v0, v1);
                } else {
                    v0 += bias0[col];
                    v1 += bias0[col + 1];
                    *(float2*)(Cout + (size_t)m * DIMC + col) = make_float2(v0, v1);
                }
            }
        }
    }
}

// ---------------- kernel 4: persistent-window attention (R12 config) -------
#define QT 64
#define NP 352
#define AQ_STR 40
#define AP_STR 360
#define ATTN_THREADS 512
#define NQT ((NSEQ + QT - 1) / QT)   // 6
#define SO_STR 33
// K 56320 + V 46080 + Q 10240 + sRedP 2048 + sOp 33792  (single buffer)
#define ATTN_SMEM ((2*NP*AQ_STR + 2*HD*AP_STR + 2*QT*AQ_STR)*2 + 2*QT*4*4 + 4*QT*SO_STR*4)

__global__ void __launch_bounds__(ATTN_THREADS, 1)
attn_kernel(const float* __restrict__ mask, const float* __restrict__ logit_scale) {
    extern __shared__ char smraw[];
    __nv_bfloat16* sKhi = (__nv_bfloat16*)smraw;
    __nv_bfloat16* sKlo = sKhi + NP * AQ_STR;
    __nv_bfloat16* sVhi = sKlo + NP * AQ_STR;
    __nv_bfloat16* sVlo = sVhi + HD * AP_STR;
    __nv_bfloat16* sQhi = sVlo + HD * AP_STR;
    __nv_bfloat16* sQlo = sQhi + QT * AQ_STR;
    float2* sRedP = (float2*)(sQlo + QT * AQ_STR);
    float* sOp = (float*)(sRedP + QT * 4);

    int h  = blockIdx.x;
    int bw = blockIdx.y;
    int tid = threadIdx.x;
    int lane = tid & 31;
    int warp = tid >> 5;
    size_t headBase = ((size_t)(bw * NHEADS + h) * NSEQ) * HD;

    const float* Kg = g_K + headBase;
    const float* Vg = g_V + headBase;
    const float* Qg = g_Q + headBase;

    int rsub = tid & 7;
    int rgrp = tid >> 3;

    // ---- K: load + normalize + split (uniform 6 iters; shfl all lanes) ----
    #pragma unroll
    for (int it = 0; it < 6; it++) {
        int r = rgrp + it * 64;
        bool ok = r < NSEQ;
        float4 v = make_float4(0.f, 0.f, 0.f, 0.f);
        if (ok) v = *(const float4*)(Kg + r * HD + rsub * 4);
        float ss = v.x * v.x + v.y * v.y + v.z * v.z + v.w * v.w;
        ss += __shfl_xor_sync(0xffffffffu, ss, 1);
        ss += __shfl_xor_sync(0xffffffffu, ss, 2);
        ss += __shfl_xor_sync(0xffffffffu, ss, 4);
        float invn = 1.f / fmaxf(sqrtf(ss), 1e-12f);
        if (ok) {
            float n0 = v.x * invn, n1 = v.y * invn, n2 = v.z * invn, n3 = v.w * invn;
            int off = r * AQ_STR + rsub * 4;
            *(uint32_t*)&sKhi[off]     = pack2_hi(n0, n1);
            *(uint32_t*)&sKhi[off + 2] = pack2_hi(n2, n3);
            *(uint32_t*)&sKlo[off]     = pack2_lo(n0, n1);
            *(uint32_t*)&sKlo[off + 2] = pack2_lo(n2, n3);
        }
    }
    for (int e = tid; e < (NP - NSEQ) * HD; e += ATTN_THREADS) {
        int r = NSEQ + (e >> 5), d = e & 31;
        sKhi[r * AQ_STR + d] = __float2bfloat16(0.f);
        sKlo[r * AQ_STR + d] = __float2bfloat16(0.f);
    }
    // ---- V: transpose + split; pad through full AP_STR ----
    for (int e = tid; e < NSEQ * HD; e += ATTN_THREADS) {
        int j = e >> 5, d = e & 31;
        float v = Vg[e];
        __nv_bfloat16 hi = __float2bfloat16(v);
        sVhi[d * AP_STR + j] = hi;
        sVlo[d * AP_STR + j] = __float2bfloat16(v - __bfloat162float(hi));
    }
    for (int e = tid; e < HD * (AP_STR - NSEQ); e += ATTN_THREADS) {
        int d = e / (AP_STR - NSEQ), j = NSEQ + e % (AP_STR - NSEQ);
        sVhi[d * AP_STR + j] = __float2bfloat16(0.f);
        sVlo[d * AP_STR + j] = __float2bfloat16(0.f);
    }
    __syncthreads();

    int wm = warp & 3;
    int wn = warp >> 2;
    uint32_t uQhi = (uint32_t)__cvta_generic_to_shared(sQhi);
    uint32_t uQlo = (uint32_t)__cvta_generic_to_shared(sQlo);
    uint32_t uKhi = (uint32_t)__cvta_generic_to_shared(sKhi);
    uint32_t uKlo = (uint32_t)__cvta_generic_to_shared(sKlo);
    uint32_t uVhi = (uint32_t)__cvta_generic_to_shared(sVhi);
    uint32_t uVlo = (uint32_t)__cvta_generic_to_shared(sVlo);

    float scale = __expf(fminf(logit_scale[h], 4.6051702f));
    int r0 = wm * 16 + (lane >> 2);

    for (int qt = 0; qt < NQT; qt++) {
        int qbase = qt * QT;

        // ---- Q tile: load + normalize(*scale) + split, one pass ----
        {
            int gi = qbase + rgrp;
            float4 v = make_float4(0.f, 0.f, 0.f, 0.f);
            if (gi < NSEQ) v = *(const float4*)(Qg + gi * HD + rsub * 4);
            float ss = v.x * v.x + v.y * v.y + v.z * v.z + v.w * v.w;
            ss += __shfl_xor_sync(0xffffffffu, ss, 1);
            ss += __shfl_xor_sync(0xffffffffu, ss, 2);
            ss += __shfl_xor_sync(0xffffffffu, ss, 4);
            float invn = scale / fmaxf(sqrtf(ss), 1e-12f);
            float n0 = v.x * invn, n1 = v.y * invn, n2 = v.z * invn, n3 = v.w * invn;
            int off = rgrp * AQ_STR + rsub * 4;
            *(uint32_t*)&sQhi[off]     = pack2_hi(n0, n1);
            *(uint32_t*)&sQhi[off + 2] = pack2_hi(n2, n3);
            *(uint32_t*)&sQlo[off]     = pack2_lo(n0, n1);
            *(uint32_t*)&sQlo[off + 2] = pack2_lo(n2, n3);
        }

        // ---- prefetch bias+mask (scalar; row bases only 4B-aligned) ----
        float2 bm[2][11];
        #pragma unroll
        for (int half = 0; half < 2; half++) {
            int gi = qbase + r0 + half * 8;
            bool rok = gi < NSEQ;
            const float* brow = g_bias + ((size_t)h * NSEQ + gi) * NSEQ;
            const float* mrow = mask + ((size_t)bw * NSEQ + gi) * NSEQ;
            #pragma unroll
            for (int t = 0; t < 11; t++) {
                int j0 = wn * 88 + t * 8 + ((lane & 3) << 1);
                float2 v = make_float2(0.f, 0.f);
                if (rok && j0 < NSEQ)     v.x = brow[j0] + mrow[j0];
                if (rok && j0 + 1 < NSEQ) v.y = brow[j0 + 1] + mrow[j0 + 1];
                bm[half][t] = v;
            }
        }
        __syncthreads();

        // ---- scores (3-pass split mma); scale folded into Q ----
        float acc[11][4];
        #pragma unroll
        for (int t = 0; t < 11; t++)
            #pragma unroll
            for (int j = 0; j < 4; j++) acc[t][j] = 0.f;
        {
            uint32_t aB[3] = {uQhi, uQhi, uQlo};
            uint32_t bB[3] = {uKhi, uKlo, uKhi};
            #pragma unroll
            for (int p = 0; p < 3; p++) {
                #pragma unroll
                for (int ks = 0; ks < 2; ks++) {
                    uint32_t a[4];
                    int arow = wm * 16 + (lane & 15);
                    int akc = ks * 16 + ((lane >> 4) << 3);
                    ldmatrix_x4(a[0], a[1], a[2], a[3], aB[p] + (arow * AQ_STR + akc) * 2);
                    int kb = ks * 16 + (((lane >> 3) & 1) << 3);
                    #pragma unroll
                    for (int t2 = 0; t2 < 5; t2++) {
                        int nrow = wn * 88 + t2 * 16 + (lane & 7) + ((lane >> 4) << 3);
                        uint32_t r0_, r1_, r2_, r3_;
                        ldmatrix_x4(r0_, r1_, r2_, r3_, bB[p] + (nrow * AQ_STR + kb) * 2);
                        uint32_t b0[2] = {r0_, r1_}, b1[2] = {r2_, r3_};
                        mma_bf16(acc[t2 * 2], a, b0);
                        mma_bf16(acc[t2 * 2 + 1], a, b1);
                    }
                    {
                        int nrow = wn * 88 + 80 + (lane & 7);
                        uint32_t r0_, r1_;
                        ldmatrix_x2(r0_, r1_, bB[p] + (nrow * AQ_STR + kb) * 2);
                        uint32_t b0[2] = {r0_, r1_};
                        mma_bf16(acc[10], a, b0);
                    }
                }
            }
        }

        // ---- online softmax: add bias, local max, exp, local sum, ONE sync --
        float mloc[2];
        #pragma unroll
        for (int half = 0; half < 2; half++) {
            int gi = qbase + r0 + half * 8;
            float m = -1e30f;
            if (gi < NSEQ) {
                #pragma unroll
                for (int t = 0; t < 11; t++) {
                    int j0 = wn * 88 + t * 8 + ((lane & 3) << 1);
                    if (j0 < NSEQ) {
                        float s = acc[t][half * 2] + bm[half][t].x;
                        acc[t][half * 2] = s;
                        m = fmaxf(m, s);
                    }
                    if (j0 + 1 < NSEQ) {
                        float s = acc[t][half * 2 + 1] + bm[half][t].y;
                        acc[t][half * 2 + 1] = s;
                        m = fmaxf(m, s);
                    }
                }
            }
            m = fmaxf(m, __shfl_xor_sync(0xffffffffu, m, 1));
            m = fmaxf(m, __shfl_xor_sync(0xffffffffu, m, 2));
            mloc[half] = m;
            float ls = 0.f;
            if (gi < NSEQ) {
                #pragma unroll
                for (int t = 0; t < 11; t++) {
                    int j0 = wn * 88 + t * 8 + ((lane & 3) << 1);
                    if (j0 < NSEQ) {
                        float p = __expf(acc[t][half * 2] - m);
                        acc[t][half * 2] = p;
                        ls += p;
                    }
                    if (j0 + 1 < NSEQ) {
                        float p = __expf(acc[t][half * 2 + 1] - m);
                        acc[t][half * 2 + 1] = p;
                        ls += p;
                    }
                }
            }
            ls += __shfl_xor_sync(0xffffffffu, ls, 1);
            ls += __shfl_xor_sync(0xffffffffu, ls, 2);
            int r = r0 + half * 8;
            if ((lane & 3) == 0) sRedP[r * 4 + wn] = make_float2(m, ls);
        }
        __syncthreads();

        // ---- combine per-warp (m, ls), fold into P scale factor ----
        float fscale[2];
        #pragma unroll
        for (int half = 0; half < 2; half++) {
            int r = r0 + half * 8;
            int gi = qbase + r;
            float2 p0 = sRedP[r * 4 + 0];
            float2 p1 = sRedP[r * 4 + 1];
            float2 p2 = sRedP[r * 4 + 2];
            float2 p3 = sRedP[r * 4 + 3];
            float mg = fmaxf(fmaxf(p0.x, p1.x), fmaxf(p2.x, p3.x));
            float total = p0.y * __expf(p0.x - mg) + p1.y * __expf(p1.x - mg)
                        + p2.y * __expf(p2.x - mg) + p3.y * __expf(p3.x - mg);
            fscale[half] = (gi < NSEQ) ? (__expf(mloc[half] - mg) / total) : 0.f;
        }

        // ---- pack P fragments in registers ----
        uint32_t phi[6][4], plo[6][4];
        #pragma unroll
        for (int ks = 0; ks < 6; ks++) {
            #pragma unroll
            for (int idx = 0; idx < 4; idx++) {
                int t = 2 * ks + (idx >> 1);
                int half = idx & 1;
                float p0 = 0.f, p1 = 0.f;
                if (t <= 10) {
                    int j0 = wn * 88 + t * 8 + ((lane & 3) << 1);
                    if (j0 < NSEQ)     p0 = acc[t][half * 2] * fscale[half];
                    if (j0 + 1 < NSEQ) p1 = acc[t][half * 2 + 1] * fscale[half];
                }
                phi[ks][idx] = pack2_hi(p0, p1);
                plo[ks][idx] = pack2_lo(p0, p1);
            }
        }

        // ---- PV: each warp over its 96-col k-slice ----
        float oacc[4][4];
        #pragma unroll
        for (int dt = 0; dt < 4; dt++)
            #pragma unroll
            for (int j = 0; j < 4; j++) oacc[dt][j] = 0.f;
        {
            int g = lane >> 3;
            int vrow_lo = (g >> 1) * 8 + (lane & 7);
            int koff = (g & 1) * 8;
            #pragma unroll
            for (int ks = 0; ks < 6; ks++) {
                int kb = wn * 88 + ks * 16 + koff;
                #pragma unroll
                for (int e = 0; e < 2; e++) {
                    int vrow = 16 * e + vrow_lo;
                    uint32_t h0, h1, h2, h3;
                    ldmatrix_x4(h0, h1, h2, h3, uVhi + (vrow * AP_STR + kb) * 2);
                    uint32_t bt0[2] = {h0, h1}, bt1[2] = {h2, h3};
                    mma_bf16(oacc[2 * e],     phi[ks], bt0);
                    mma_bf16(oacc[2 * e + 1], phi[ks], bt1);
                    mma_bf16(oacc[2 * e],     plo[ks], bt0);
                    mma_bf16(oacc[2 * e + 1], plo[ks], bt1);
                    uint32_t l0, l1, l2, l3;
                    ldmatrix_x4(l0, l1, l2, l3, uVlo + (vrow * AP_STR + kb) * 2);
                    uint32_t bl0[2] = {l0, l1}, bl1[2] = {l2, l3};
                    mma_bf16(oacc[2 * e],     phi[ks], bl0);
                    mma_bf16(oacc[2 * e + 1], phi[ks], bl1);
                }
            }
        }
        #pragma unroll
        for (int dt = 0; dt < 4; dt++) {
            int d0 = dt * 8 + ((lane & 3) << 1);
            #pragma unroll
            for (int half = 0; half < 2; half++) {
                int r = r0 + half * 8;
                float* dst = sOp + wn * (QT * SO_STR) + r * SO_STR + d0;
                dst[0] = oacc[dt][half * 2];
                dst[1] = oacc[dt][half * 2 + 1];
            }
        }
        __syncthreads();

        // ---- store O tile (sum 4 partials, split bf16) ----
        for (int o = tid; o < QT * HD; o += ATTN_THREADS) {
            int row = o >> 5, d = o & 31;
            int gi = qbase + row;
            if (gi >= NSEQ) continue;
            int base = row * SO_STR + d;
            float v = sOp[base]
                    + sOp[1 * (QT * SO_STR) + base]
                    + sOp[2 * (QT * SO_STR) + base]
                    + sOp[3 * (QT * SO_STR) + base];
            size_t oidx = ((size_t)bw * NSEQ + gi) * DIMC + h * HD + d;
            __nv_bfloat16 hv = __float2bfloat16(v);
            g_Ohi[oidx] = hv;
            g_Olo[oidx] = __float2bfloat16(v - __bfloat162float(hv));
        }
        __syncthreads();
    }
}

// ---------------- launch -----------------------------------------------------
extern "C" void kernel_launch(void* const* d_in, const int* in_sizes, int n_in,
                              void* d_out, int out_size) {
    const float* x        = (const float*)d_in[0];
    const float* mask     = (const float*)d_in[1];
    const float* qkv_w    = (const float*)d_in[2];
    const float* q_bias   = (const float*)d_in[3];
    const float* v_bias   = (const float*)d_in[4];
    const float* lscale   = (const float*)d_in[5];
    const float* cpb_w1   = (const float*)d_in[6];
    const float* cpb_b1   = (const float*)d_in[7];
    const float* cpb_w2   = (const float*)d_in[8];
    const float* proj_w   = (const float*)d_in[9];
    const float* proj_b   = (const float*)d_in[10];
    const float* rel_tab  = (const float*)d_in[11];
    const int*   rel_idx  = (const int*)d_in[12];
    float* out = (float*)d_out;

    const int M = MTOT;

    split_all_kernel<<<(N4_ALL + 255) / 256, 256>>>(x, qkv_w, proj_w);

    cpb_table_kernel<<<TABSZ, CPBH>>>(rel_tab, cpb_w1, cpb_b1, cpb_w2);

    {
        int total = NHEADS * NSEQ * NSEQ;
        bias_gather_kernel<<<(total + 255) / 256, 256>>>(rel_idx);
    }

    {
        cudaFuncSetAttribute(mma_gemm_kernel<0>,
                             cudaFuncAttributeMaxDynamicSharedMemorySize, GEMM_SMEM);
        dim3 grid((M + GBM - 1) / GBM, QKV_N / GBN);
        mma_gemm_kernel<0><<<grid, 256, GEMM_SMEM>>>(q_bias, v_bias, nullptr, M);
    }

    {
        cudaFuncSetAttribute(attn_kernel,
                             cudaFuncAttributeMaxDynamicSharedMemorySize, ATTN_SMEM);
        dim3 grid(NHEADS, BATCH);
        attn_kernel<<<grid, ATTN_THREADS, ATTN_SMEM>>>(mask, lscale);
    }

    {
        cudaFuncSetAttribute(mma_gemm_kernel<1>,
                             cudaFuncAttributeMaxDynamicSharedMemorySize, GEMM_SMEM);
        dim3 grid((M + GBM - 1) / GBM, DIMC / GBN);
        mma_gemm_kernel<1><<<grid, 256, GEMM_SMEM>>>(proj_b, nullptr, out, M);
    }
}

// round 16
// speedup vs baseline: 1.0839x; 1.0531x over previous
#include <cuda_runtime.h>
#include <cuda_bf16.h>
#include <math.h>
#include <stdint.h>

// ---------------- problem constants ----------------
#define BATCH   64
#define NSEQ    343
#define DIMC    384
#define NHEADS  12
#define HD      32
#define KDIM    384
#define QKV_N   1152
#define TABSZ   2197
#define CPBH    512
#define MTOT    (BATCH * NSEQ)      // 21952

// ---------------- scratch ----------------
__device__ float g_Q[(size_t)BATCH * NHEADS * NSEQ * HD];
__device__ float g_K[(size_t)BATCH * NHEADS * NSEQ * HD];
__device__ float g_V[(size_t)BATCH * NHEADS * NSEQ * HD];
__device__ float g_bias[(size_t)NHEADS * NSEQ * NSEQ];
__device__ float g_tableH[(size_t)TABSZ * NHEADS];

__device__ __nv_bfloat16 g_xhi[(size_t)MTOT * KDIM];
__device__ __nv_bfloat16 g_xlo[(size_t)MTOT * KDIM];
__device__ __nv_bfloat16 g_wqhi[(size_t)QKV_N * KDIM];
__device__ __nv_bfloat16 g_wqlo[(size_t)QKV_N * KDIM];
__device__ __nv_bfloat16 g_pwhi[(size_t)DIMC * KDIM];
__device__ __nv_bfloat16 g_pwlo[(size_t)DIMC * KDIM];
__device__ __nv_bfloat16 g_Ohi[(size_t)MTOT * DIMC];
__device__ __nv_bfloat16 g_Olo[(size_t)MTOT * DIMC];

__device__ __forceinline__ float warpSum(float v) {
    #pragma unroll
    for (int o = 16; o > 0; o >>= 1) v += __shfl_xor_sync(0xffffffffu, v, o);
    return v;
}

// ---------------- mma / async helpers ----------------
__device__ __forceinline__ void ldmatrix_x4(uint32_t& r0, uint32_t& r1,
                                            uint32_t& r2, uint32_t& r3, uint32_t addr) {
    asm volatile("ldmatrix.sync.aligned.m8n8.x4.shared.b16 {%0,%1,%2,%3}, [%4];"
        : "=r"(r0), "=r"(r1), "=r"(r2), "=r"(r3) : "r"(addr));
}
__device__ __forceinline__ void ldmatrix_x2(uint32_t& r0, uint32_t& r1, uint32_t addr) {
    asm volatile("ldmatrix.sync.aligned.m8n8.x2.shared.b16 {%0,%1}, [%2];"
        : "=r"(r0), "=r"(r1) : "r"(addr));
}
__device__ __forceinline__ void mma_bf16(float* c, const uint32_t* a, const uint32_t* b) {
    asm volatile("mma.sync.aligned.m16n8k16.row.col.f32.bf16.bf16.f32 "
        "{%0,%1,%2,%3}, {%4,%5,%6,%7}, {%8,%9}, {%0,%1,%2,%3};"
        : "+f"(c[0]), "+f"(c[1]), "+f"(c[2]), "+f"(c[3])
        : "r"(a[0]), "r"(a[1]), "r"(a[2]), "r"(a[3]), "r"(b[0]), "r"(b[1]));
}
__device__ __forceinline__ uint32_t pack2_hi(float a, float b) {
    __nv_bfloat162 t(__float2bfloat16(a), __float2bfloat16(b));
    return *(uint32_t*)&t;
}
__device__ __forceinline__ uint32_t pack2_lo(float a, float b) {
    float ha = __bfloat162float(__float2bfloat16(a));
    float hb = __bfloat162float(__float2bfloat16(b));
    __nv_bfloat162 t(__float2bfloat16(a - ha), __float2bfloat16(b - hb));
    return *(uint32_t*)&t;
}
__device__ __forceinline__ void cp_async16(uint32_t dst, const void* src, bool pred) {
    int sz = pred ? 16 : 0;
    asm volatile("cp.async.cg.shared.global [%0], [%1], 16, %2;"
        :: "r"(dst), "l"(src), "r"(sz));
}
__device__ __forceinline__ void cp_commit() {
    asm volatile("cp.async.commit_group;");
}
template <int N>
__device__ __forceinline__ void cp_wait() {
    asm volatile("cp.async.wait_group %0;" :: "n"(N));
}

// ---------------- fused split kernel: x | qkv_w | proj_w ------------------
#define N4_X   (MTOT * KDIM / 4)
#define N4_WQ  (QKV_N * KDIM / 4)
#define N4_PW  (DIMC * KDIM / 4)
#define N4_ALL (N4_X + N4_WQ + N4_PW)

__global__ void split_all_kernel(const float* __restrict__ x,
                                 const float* __restrict__ qkv_w,
                                 const float* __restrict__ proj_w) {
    int i = blockIdx.x * blockDim.x + threadIdx.x;
    if (i >= N4_ALL) return;
    const float* src;
    __nv_bfloat16 *hi, *lo;
    int k;
    if (i < N4_X) {
        src = x; hi = g_xhi; lo = g_xlo; k = i;
    } else if (i < N4_X + N4_WQ) {
        src = qkv_w; hi = g_wqhi; lo = g_wqlo; k = i - N4_X;
    } else {
        src = proj_w; hi = g_pwhi; lo = g_pwlo; k = i - N4_X - N4_WQ;
    }
    float4 v = ((const float4*)src)[k];
    __nv_bfloat16 h0 = __float2bfloat16(v.x);
    __nv_bfloat16 h1 = __float2bfloat16(v.y);
    __nv_bfloat16 h2 = __float2bfloat16(v.z);
    __nv_bfloat16 h3 = __float2bfloat16(v.w);
    __nv_bfloat162* hp = (__nv_bfloat162*)(hi + (size_t)k * 4);
    __nv_bfloat162* lp = (__nv_bfloat162*)(lo + (size_t)k * 4);
    hp[0] = __nv_bfloat162(h0, h1);
    hp[1] = __nv_bfloat162(h2, h3);
    lp[0] = __nv_bfloat162(__float2bfloat16(v.x - __bfloat162float(h0)),
                           __float2bfloat16(v.y - __bfloat162float(h1)));
    lp[1] = __nv_bfloat162(__float2bfloat16(v.z - __bfloat162float(h2)),
                           __float2bfloat16(v.w - __bfloat162float(h3)));
}

// ---------------- kernel 1: CPB MLP ----------------
__global__ void cpb_table_kernel(const float* __restrict__ tab,
                                 const float* __restrict__ w1,
                                 const float* __restrict__ b1,
                                 const float* __restrict__ w2) {
    __shared__ float hid[CPBH];
    int r = blockIdx.x;
    int tid = threadIdx.x;
    float t0 = tab[r * 3 + 0], t1 = tab[r * 3 + 1], t2 = tab[r * 3 + 2];
    float h = fmaf(w1[tid * 3 + 0], t0,
              fmaf(w1[tid * 3 + 1], t1,
              fmaf(w1[tid * 3 + 2], t2, b1[tid])));
    hid[tid] = fmaxf(h, 0.f);
    __syncthreads();
    int warp = tid >> 5, lane = tid & 31;
    if (warp < NHEADS) {
        float s = 0.f;
        #pragma unroll
        for (int j = lane; j < CPBH; j += 32) s = fmaf(hid[j], w2[warp * CPBH + j], s);
        s = warpSum(s);
        if (lane == 0) g_tableH[r * NHEADS + warp] = s;
    }
}

// ---------------- kernel 2: bias gather ----------------
__global__ void bias_gather_kernel(const int* __restrict__ idx) {
    int t = blockIdx.x * blockDim.x + threadIdx.x;
    const int NN = NSEQ * NSEQ;
    if (t >= NHEADS * NN) return;
    int h = t / NN;
    int ij = t - h * NN;
    float v = g_tableH[idx[ij] * NHEADS + h];
    g_bias[t] = 16.f / (1.f + __expf(-v));
}

// ---------------- tensor-core GEMM, fused-pass cp.async pipeline ----------
// Phase A (chunks 0-11):  stage {Ahi, Bhi, Blo}; compute Ahi*Bhi + Ahi*Blo
// Phase B (chunks 12-23): stage {Alo, Bhi};      compute Alo*Bhi
#define GBM 128
#define GBN 128
#define GBK 32
#define TSTR 40
#define GSTAGES 3
#define GTILEB (GBM * TSTR * 2)          // 10240 bytes per tile
#define GSTAGEB (3 * GTILEB)             // A + B0 + B1 slots
#define GEMM_SMEM (GSTAGES * GSTAGEB)    // 92160
#define NKCH (KDIM / GBK)                // 12
#define NCHT (2 * NKCH)                  // 24

template <int MODE>
__global__ void __launch_bounds__(256, 2)
mma_gemm_kernel(const float* __restrict__ bias0, const float* __restrict__ bias1,
                float* __restrict__ Cout, int M) {
    const __nv_bfloat16* Ahi = (MODE == 0) ? g_xhi : g_Ohi;
    const __nv_bfloat16* Alo = (MODE == 0) ? g_xlo : g_Olo;
    const __nv_bfloat16* Bhi = (MODE == 0) ? g_wqhi : g_pwhi;
    const __nv_bfloat16* Blo = (MODE == 0) ? g_wqlo : g_pwlo;

    extern __shared__ char gsm[];
    uint32_t sBase = (uint32_t)__cvta_generic_to_shared(gsm);

    int tid = threadIdx.x;
    int lane = tid & 31;
    int warp = tid >> 5;
    int wm = warp >> 2;
    int wn = warp & 3;
    int bm = blockIdx.x * GBM;
    int bn = blockIdx.y * GBN;

    int lrow = tid >> 1;
    int lk16 = (tid & 1) * 16;
    bool arow_ok = (bm + lrow) < M;

    float acc[16][4];
    #pragma unroll
    for (int t = 0; t < 16; t++)
        #pragma unroll
        for (int j = 0; j < 4; j++) acc[t][j] = 0.f;

    // issue chunk c into stage s
    auto issue = [&](int c, int s) {
        int phase = c / NKCH;                  // 0 = A, 1 = B
        int kc = (c % NKCH) * GBK;
        uint32_t st = sBase + s * GSTAGEB + (lrow * TSTR + lk16) * 2;
        const __nv_bfloat16* Ap = (phase == 0 ? Ahi : Alo)
                                  + (size_t)(bm + lrow) * KDIM + kc + lk16;
        const __nv_bfloat16* B0 = Bhi + (size_t)(bn + lrow) * KDIM + kc + lk16;
        cp_async16(st, Ap, arow_ok);
        cp_async16(st + 16, Ap + 8, arow_ok);
        cp_async16(st + GTILEB, B0, true);
        cp_async16(st + GTILEB + 16, B0 + 8, true);
        if (phase == 0) {
            const __nv_bfloat16* B1 = Blo + (size_t)(bn + lrow) * KDIM + kc + lk16;
            cp_async16(st + 2 * GTILEB, B1, true);
            cp_async16(st + 2 * GTILEB + 16, B1 + 8, true);
        }
        cp_commit();
    };

    issue(0, 0);
    issue(1, 1);

    for (int it = 0; it < NCHT; it++) {
        if (it < NCHT - 1) cp_wait<1>(); else cp_wait<0>();
        __syncthreads();
        if (it + 2 < NCHT) issue(it + 2, (it + 2) % GSTAGES);

        int phase = it / NKCH;
        uint32_t baseA  = sBase + (it % GSTAGES) * GSTAGEB;
        uint32_t baseB0 = baseA + GTILEB;
        uint32_t baseB1 = baseA + 2 * GTILEB;
        #pragma unroll
        for (int ks = 0; ks < 2; ks++) {
            uint32_t af[4][4];
            #pragma unroll
            for (int mi = 0; mi < 4; mi++) {
                int row = wm * 64 + mi * 16 + (lane & 15);
                int kb = ks * 16 + ((lane >> 4) << 3);
                ldmatrix_x4(af[mi][0], af[mi][1], af[mi][2], af[mi][3],
                            baseA + (row * TSTR + kb) * 2);
            }
            // B-hi fragments
            {
                uint32_t bfr[4][2];
                #pragma unroll
                for (int bj = 0; bj < 2; bj++) {
                    int nrow = wn * 32 + bj * 16 + (lane & 7) + ((lane >> 4) << 3);
                    int kb = ks * 16 + (((lane >> 3) & 1) << 3);
                    uint32_t r0, r1, r2, r3;
                    ldmatrix_x4(r0, r1, r2, r3, baseB0 + (nrow * TSTR + kb) * 2);
                    bfr[bj * 2][0] = r0; bfr[bj * 2][1] = r1;
                    bfr[bj * 2 + 1][0] = r2; bfr[bj * 2 + 1][1] = r3;
                }
                #pragma unroll
                for (int mi = 0; mi < 4; mi++)
                    #pragma unroll
                    for (int nj = 0; nj < 4; nj++)
                        mma_bf16(acc[mi * 4 + nj], af[mi], bfr[nj]);
            }
            // B-lo fragments (phase A only)
            if (phase == 0) {
                uint32_t bfr[4][2];
                #pragma unroll
                for (int bj = 0; bj < 2; bj++) {
                    int nrow = wn * 32 + bj * 16 + (lane & 7) + ((lane >> 4) << 3);
                    int kb = ks * 16 + (((lane >> 3) & 1) << 3);
                    uint32_t r0, r1, r2, r3;
                    ldmatrix_x4(r0, r1, r2, r3, baseB1 + (nrow * TSTR + kb) * 2);
                    bfr[bj * 2][0] = r0; bfr[bj * 2][1] = r1;
                    bfr[bj * 2 + 1][0] = r2; bfr[bj * 2 + 1][1] = r3;
                }
                #pragma unroll
                for (int mi = 0; mi < 4; mi++)
                    #pragma unroll
                    for (int nj = 0; nj < 4; nj++)
                        mma_bf16(acc[mi * 4 + nj], af[mi], bfr[nj]);
            }
        }
    }

    #pragma unroll
    for (int mi = 0; mi < 4; mi++) {
        #pragma unroll
        for (int nj = 0; nj < 4; nj++) {
            int col = bn + wn * 32 + nj * 8 + ((lane & 3) << 1);
            float* cr = acc[mi * 4 + nj];
            #pragma unroll
            for (int half = 0; half < 2; half++) {
                int m = bm + wm * 64 + mi * 16 + (lane >> 2) + half * 8;
                if (m >= M) continue;
                float v0 = cr[half * 2 + 0];
                float v1 = cr[half * 2 + 1];
                if (MODE == 0) {
                    int part = col / DIMC;
                    int oc = col - part * DIMC;
                    int hh = oc >> 5, d = oc & 31;
                    if (part == 0) { v0 += bias0[oc]; v1 += bias0[oc + 1]; }
                    else if (part == 2) { v0 += bias1[oc]; v1 += bias1[oc + 1]; }
                    int bw = m / NSEQ, nn = m - bw * NSEQ;
                    size_t dst = ((size_t)(bw * NHEADS + hh) * NSEQ + nn) * HD + d;
                    float* tgt = (part == 0) ? g_Q : (part == 1 ? g_K : g_V);
                    *(float2*)(tgt + dst) = make_float2(v0, v1);
                } else {
                    v0 += bias0[col];
                    v1 += bias0[col + 1];
                    *(float2*)(Cout + (size_t)m * DIMC + col) = make_float2(v0, v1);
                }
            }
        }
    }
}

// ---------------- kernel 4: persistent-window attention (R12 config) -------
#define QT 64
#define NP 352
#define AQ_STR 40
#define AP_STR 360
#define ATTN_THREADS 512
#define NQT ((NSEQ + QT - 1) / QT)   // 6
#define SO_STR 33
#define ATTN_SMEM ((2*NP*AQ_STR + 2*HD*AP_STR + 2*QT*AQ_STR)*2 + 2*QT*4*4 + 4*QT*SO_STR*4)

__global__ void __launch_bounds__(ATTN_THREADS, 1)
attn_kernel(const float* __restrict__ mask, const float* __restrict__ logit_scale) {
    extern __shared__ char smraw[];
    __nv_bfloat16* sKhi = (__nv_bfloat16*)smraw;
    __nv_bfloat16* sKlo = sKhi + NP * AQ_STR;
    __nv_bfloat16* sVhi = sKlo + NP * AQ_STR;
    __nv_bfloat16* sVlo = sVhi + HD * AP_STR;
    __nv_bfloat16* sQhi = sVlo + HD * AP_STR;
    __nv_bfloat16* sQlo = sQhi + QT * AQ_STR;
    float2* sRedP = (float2*)(sQlo + QT * AQ_STR);
    float* sOp = (float*)(sRedP + QT * 4);

    int h  = blockIdx.x;
    int bw = blockIdx.y;
    int tid = threadIdx.x;
    int lane = tid & 31;
    int warp = tid >> 5;
    size_t headBase = ((size_t)(bw * NHEADS + h) * NSEQ) * HD;

    const float* Kg = g_K + headBase;
    const float* Vg = g_V + headBase;
    const float* Qg = g_Q + headBase;

    int rsub = tid & 7;
    int rgrp = tid >> 3;

    #pragma unroll
    for (int it = 0; it < 6; it++) {
        int r = rgrp + it * 64;
        bool ok = r < NSEQ;
        float4 v = make_float4(0.f, 0.f, 0.f, 0.f);
        if (ok) v = *(const float4*)(Kg + r * HD + rsub * 4);
        float ss = v.x * v.x + v.y * v.y + v.z * v.z + v.w * v.w;
        ss += __shfl_xor_sync(0xffffffffu, ss, 1);
        ss += __shfl_xor_sync(0xffffffffu, ss, 2);
        ss += __shfl_xor_sync(0xffffffffu, ss, 4);
        float invn = 1.f / fmaxf(sqrtf(ss), 1e-12f);
        if (ok) {
            float n0 = v.x * invn, n1 = v.y * invn, n2 = v.z * invn, n3 = v.w * invn;
            int off = r * AQ_STR + rsub * 4;
            *(uint32_t*)&sKhi[off]     = pack2_hi(n0, n1);
            *(uint32_t*)&sKhi[off + 2] = pack2_hi(n2, n3);
            *(uint32_t*)&sKlo[off]     = pack2_lo(n0, n1);
            *(uint32_t*)&sKlo[off + 2] = pack2_lo(n2, n3);
        }
    }
    for (int e = tid; e < (NP - NSEQ) * HD; e += ATTN_THREADS) {
        int r = NSEQ + (e >> 5), d = e & 31;
        sKhi[r * AQ_STR + d] = __float2bfloat16(0.f);
        sKlo[r * AQ_STR + d] = __float2bfloat16(0.f);
    }
    for (int e = tid; e < NSEQ * HD; e += ATTN_THREADS) {
        int j = e >> 5, d = e & 31;
        float v = Vg[e];
        __nv_bfloat16 hi = __float2bfloat16(v);
        sVhi[d * AP_STR + j] = hi;
        sVlo[d * AP_STR + j] = __float2bfloat16(v - __bfloat162float(hi));
    }
    for (int e = tid; e < HD * (AP_STR - NSEQ); e += ATTN_THREADS) {
        int d = e / (AP_STR - NSEQ), j = NSEQ + e % (AP_STR - NSEQ);
        sVhi[d * AP_STR + j] = __float2bfloat16(0.f);
        sVlo[d * AP_STR + j] = __float2bfloat16(0.f);
    }
    __syncthreads();

    int wm = warp & 3;
    int wn = warp >> 2;
    uint32_t uQhi = (uint32_t)__cvta_generic_to_shared(sQhi);
    uint32_t uQlo = (uint32_t)__cvta_generic_to_shared(sQlo);
    uint32_t uKhi = (uint32_t)__cvta_generic_to_shared(sKhi);
    uint32_t uKlo = (uint32_t)__cvta_generic_to_shared(sKlo);
    uint32_t uVhi = (uint32_t)__cvta_generic_to_shared(sVhi);
    uint32_t uVlo = (uint32_t)__cvta_generic_to_shared(sVlo);

    float scale = __expf(fminf(logit_scale[h], 4.6051702f));
    int r0 = wm * 16 + (lane >> 2);

    for (int qt = 0; qt < NQT; qt++) {
        int qbase = qt * QT;

        {
            int gi = qbase + rgrp;
            float4 v = make_float4(0.f, 0.f, 0.f, 0.f);
            if (gi < NSEQ) v = *(const float4*)(Qg + gi * HD + rsub * 4);
            float ss = v.x * v.x + v.y * v.y + v.z * v.z + v.w * v.w;
            ss += __shfl_xor_sync(0xffffffffu, ss, 1);
            ss += __shfl_xor_sync(0xffffffffu, ss, 2);
            ss += __shfl_xor_sync(0xffffffffu, ss, 4);
            float invn = scale / fmaxf(sqrtf(ss), 1e-12f);
            float n0 = v.x * invn, n1 = v.y * invn, n2 = v.z * invn, n3 = v.w * invn;
            int off = rgrp * AQ_STR + rsub * 4;
            *(uint32_t*)&sQhi[off]     = pack2_hi(n0, n1);
            *(uint32_t*)&sQhi[off + 2] = pack2_hi(n2, n3);
            *(uint32_t*)&sQlo[off]     = pack2_lo(n0, n1);
            *(uint32_t*)&sQlo[off + 2] = pack2_lo(n2, n3);
        }

        float2 bm[2][11];
        #pragma unroll
        for (int half = 0; half < 2; half++) {
            int gi = qbase + r0 + half * 8;
            bool rok = gi < NSEQ;
            const float* brow = g_bias + ((size_t)h * NSEQ + gi) * NSEQ;
            const float* mrow = mask + ((size_t)bw * NSEQ + gi) * NSEQ;
            #pragma unroll
            for (int t = 0; t < 11; t++) {
                int j0 = wn * 88 + t * 8 + ((lane & 3) << 1);
                float2 v = make_float2(0.f, 0.f);
                if (rok && j0 < NSEQ)     v.x = brow[j0] + mrow[j0];
                if (rok && j0 + 1 < NSEQ) v.y = brow[j0 + 1] + mrow[j0 + 1];
                bm[half][t] = v;
            }
        }
        __syncthreads();

        float acc[11][4];
        #pragma unroll
        for (int t = 0; t < 11; t++)
            #pragma unroll
            for (int j = 0; j < 4; j++) acc[t][j] = 0.f;
        {
            uint32_t aB[3] = {uQhi, uQhi, uQlo};
            uint32_t bB[3] = {uKhi, uKlo, uKhi};
            #pragma unroll
            for (int p = 0; p < 3; p++) {
                #pragma unroll
                for (int ks = 0; ks < 2; ks++) {
                    uint32_t a[4];
                    int arow = wm * 16 + (lane & 15);
                    int akc = ks * 16 + ((lane >> 4) << 3);
                    ldmatrix_x4(a[0], a[1], a[2], a[3], aB[p] + (arow * AQ_STR + akc) * 2);
                    int kb = ks * 16 + (((lane >> 3) & 1) << 3);
                    #pragma unroll
                    for (int t2 = 0; t2 < 5; t2++) {
                        int nrow = wn * 88 + t2 * 16 + (lane & 7) + ((lane >> 4) << 3);
                        uint32_t r0_, r1_, r2_, r3_;
                        ldmatrix_x4(r0_, r1_, r2_, r3_, bB[p] + (nrow * AQ_STR + kb) * 2);
                        uint32_t b0[2] = {r0_, r1_}, b1[2] = {r2_, r3_};
                        mma_bf16(acc[t2 * 2], a, b0);
                        mma_bf16(acc[t2 * 2 + 1], a, b1);
                    }
                    {
                        int nrow = wn * 88 + 80 + (lane & 7);
                        uint32_t r0_, r1_;
                        ldmatrix_x2(r0_, r1_, bB[p] + (nrow * AQ_STR + kb) * 2);
                        uint32_t b0[2] = {r0_, r1_};
                        mma_bf16(acc[10], a, b0);
                    }
                }
            }
        }

        float mloc[2];
        #pragma unroll
        for (int half = 0; half < 2; half++) {
            int gi = qbase + r0 + half * 8;
            float m = -1e30f;
            if (gi < NSEQ) {
                #pragma unroll
                for (int t = 0; t < 11; t++) {
                    int j0 = wn * 88 + t * 8 + ((lane & 3) << 1);
                    if (j0 < NSEQ) {
                        float s = acc[t][half * 2] + bm[half][t].x;
                        acc[t][half * 2] = s;
                        m = fmaxf(m, s);
                    }
                    if (j0 + 1 < NSEQ) {
                        float s = acc[t][half * 2 + 1] + bm[half][t].y;
                        acc[t][half * 2 + 1] = s;
                        m = fmaxf(m, s);
                    }
                }
            }
            m = fmaxf(m, __shfl_xor_sync(0xffffffffu, m, 1));
            m = fmaxf(m, __shfl_xor_sync(0xffffffffu, m, 2));
            mloc[half] = m;
            float ls = 0.f;
            if (gi < NSEQ) {
                #pragma unroll
                for (int t = 0; t < 11; t++) {
                    int j0 = wn * 88 + t * 8 + ((lane & 3) << 1);
                    if (j0 < NSEQ) {
                        float p = __expf(acc[t][half * 2] - m);
                        acc[t][half * 2] = p;
                        ls += p;
                    }
                    if (j0 + 1 < NSEQ) {
                        float p = __expf(acc[t][half * 2 + 1] - m);
                        acc[t][half * 2 + 1] = p;
                        ls += p;
                    }
                }
            }
            ls += __shfl_xor_sync(0xffffffffu, ls, 1);
            ls += __shfl_xor_sync(0xffffffffu, ls, 2);
            int r = r0 + half * 8;
            if ((lane & 3) == 0) sRedP[r * 4 + wn] = make_float2(m, ls);
        }
        __syncthreads();

        float fscale[2];
        #pragma unroll
        for (int half = 0; half < 2; half++) {
            int r = r0 + half * 8;
            int gi = qbase + r;
            float2 p0 = sRedP[r * 4 + 0];
            float2 p1 = sRedP[r * 4 + 1];
            float2 p2 = sRedP[r * 4 + 2];
            float2 p3 = sRedP[r * 4 + 3];
            float mg = fmaxf(fmaxf(p0.x, p1.x), fmaxf(p2.x, p3.x));
            float total = p0.y * __expf(p0.x - mg) + p1.y * __expf(p1.x - mg)
                        + p2.y * __expf(p2.x - mg) + p3.y * __expf(p3.x - mg);
            fscale[half] = (gi < NSEQ) ? (__expf(mloc[half] - mg) / total) : 0.f;
        }

        uint32_t phi[6][4], plo[6][4];
        #pragma unroll
        for (int ks = 0; ks < 6; ks++) {
            #pragma unroll
            for (int idx = 0; idx < 4; idx++) {
                int t = 2 * ks + (idx >> 1);
                int half = idx & 1;
                float p0 = 0.f, p1 = 0.f;
                if (t <= 10) {
                    int j0 = wn * 88 + t * 8 + ((lane & 3) << 1);
                    if (j0 < NSEQ)     p0 = acc[t][half * 2] * fscale[half];
                    if (j0 + 1 < NSEQ) p1 = acc[t][half * 2 + 1] * fscale[half];
                }
                phi[ks][idx] = pack2_hi(p0, p1);
                plo[ks][idx] = pack2_lo(p0, p1);
            }
        }

        float oacc[4][4];
        #pragma unroll
        for (int dt = 0; dt < 4; dt++)
            #pragma unroll
            for (int j = 0; j < 4; j++) oacc[dt][j] = 0.f;
        {
            int g = lane >> 3;
            int vrow_lo = (g >> 1) * 8 + (lane & 7);
            int koff = (g & 1) * 8;
            #pragma unroll
            for (int ks = 0; ks < 6; ks++) {
                int kb = wn * 88 + ks * 16 + koff;
                #pragma unroll
                for (int e = 0; e < 2; e++) {
                    int vrow = 16 * e + vrow_lo;
                    uint32_t h0, h1, h2, h3;
                    ldmatrix_x4(h0, h1, h2, h3, uVhi + (vrow * AP_STR + kb) * 2);
                    uint32_t bt0[2] = {h0, h1}, bt1[2] = {h2, h3};
                    mma_bf16(oacc[2 * e],     phi[ks], bt0);
                    mma_bf16(oacc[2 * e + 1], phi[ks], bt1);
                    mma_bf16(oacc[2 * e],     plo[ks], bt0);
                    mma_bf16(oacc[2 * e + 1], plo[ks], bt1);
                    uint32_t l0, l1, l2, l3;
                    ldmatrix_x4(l0, l1, l2, l3, uVlo + (vrow * AP_STR + kb) * 2);
                    uint32_t bl0[2] = {l0, l1}, bl1[2] = {l2, l3};
                    mma_bf16(oacc[2 * e],     phi[ks], bl0);
                    mma_bf16(oacc[2 * e + 1], phi[ks], bl1);
                }
            }
        }
        #pragma unroll
        for (int dt = 0; dt < 4; dt++) {
            int d0 = dt * 8 + ((lane & 3) << 1);
            #pragma unroll
            for (int half = 0; half < 2; half++) {
                int r = r0 + half * 8;
                float* dst = sOp + wn * (QT * SO_STR) + r * SO_STR + d0;
                dst[0] = oacc[dt][half * 2];
                dst[1] = oacc[dt][half * 2 + 1];
            }
        }
        __syncthreads();

        for (int o = tid; o < QT * HD; o += ATTN_THREADS) {
            int row = o >> 5, d = o & 31;
            int gi = qbase + row;
            if (gi >= NSEQ) continue;
            int base = row * SO_STR + d;
            float v = sOp[base]
                    + sOp[1 * (QT * SO_STR) + base]
                    + sOp[2 * (QT * SO_STR) + base]
                    + sOp[3 * (QT * SO_STR) + base];
            size_t oidx = ((size_t)bw * NSEQ + gi) * DIMC + h * HD + d;
            __nv_bfloat16 hv = __float2bfloat16(v);
            g_Ohi[oidx] = hv;
            g_Olo[oidx] = __float2bfloat16(v - __bfloat162float(hv));
        }
        __syncthreads();
    }
}

// ---------------- launch -----------------------------------------------------
extern "C" void kernel_launch(void* const* d_in, const int* in_sizes, int n_in,
                              void* d_out, int out_size) {
    const float* x        = (const float*)d_in[0];
    const float* mask     = (const float*)d_in[1];
    const float* qkv_w    = (const float*)d_in[2];
    const float* q_bias   = (const float*)d_in[3];
    const float* v_bias   = (const float*)d_in[4];
    const float* lscale   = (const float*)d_in[5];
    const float* cpb_w1   = (const float*)d_in[6];
    const float* cpb_b1   = (const float*)d_in[7];
    const float* cpb_w2   = (const float*)d_in[8];
    const float* proj_w   = (const float*)d_in[9];
    const float* proj_b   = (const float*)d_in[10];
    const float* rel_tab  = (const float*)d_in[11];
    const int*   rel_idx  = (const int*)d_in[12];
    float* out = (float*)d_out;

    const int M = MTOT;

    split_all_kernel<<<(N4_ALL + 255) / 256, 256>>>(x, qkv_w, proj_w);

    cpb_table_kernel<<<TABSZ, CPBH>>>(rel_tab, cpb_w1, cpb_b1, cpb_w2);

    {
        int total = NHEADS * NSEQ * NSEQ;
        bias_gather_kernel<<<(total + 255) / 256, 256>>>(rel_idx);
    }

    {
        cudaFuncSetAttribute(mma_gemm_kernel<0>,
                             cudaFuncAttributeMaxDynamicSharedMemorySize, GEMM_SMEM);
        dim3 grid((M + GBM - 1) / GBM, QKV_N / GBN);
        mma_gemm_kernel<0><<<grid, 256, GEMM_SMEM>>>(q_bias, v_bias, nullptr, M);
    }

    {
        cudaFuncSetAttribute(attn_kernel,
                             cudaFuncAttributeMaxDynamicSharedMemorySize, ATTN_SMEM);
        dim3 grid(NHEADS, BATCH);
        attn_kernel<<<grid, ATTN_THREADS, ATTN_SMEM>>>(mask, lscale);
    }

    {
        cudaFuncSetAttribute(mma_gemm_kernel<1>,
                             cudaFuncAttributeMaxDynamicSharedMemorySize, GEMM_SMEM);
        dim3 grid((M + GBM - 1) / GBM, DIMC / GBN);
        mma_gemm_kernel<1><<<grid, 256, GEMM_SMEM>>>(proj_b, nullptr, out, M);
    }
}